// round 10
// baseline (speedup 1.0000x reference)
#include <cuda_runtime.h>

// Problem constants (UP=3, DOWN=2, Lh=63, Lb=51)
#define R_OUT 8                    // same-phase outputs per thread
#define BLOCK_T 384                // 3 phase groups x 128 threads
#define OUT_PER_BLOCK 3072         // 3 * 128 * R_OUT
#define TILE_X 2112                // logical floats per block (need 2107, even)
#define OS_LOG 3072
#define SBUF_SZ 3200               // union: max(XP(TILE_X)=2376, 3072+3072/24=3200)
#define NSTEP 30                   // packed coefficient steps per phase

// xs swizzle: pad TWO floats per 16 -> lane logical stride 16 becomes phys
// stride 18 (72B; bank-pair 9*l mod 16, gcd(9,16)=1 -> LDS.64 conflict-free),
// 8B alignment preserved. Base 16*l is a multiple of 16, so:
// XP(16l + c) = 18l + XPOFF(c).
#define XP(i)    ((i) + (((i) >> 4) << 1))
#define XPOFF(c) ((c) + (((c) >> 4) << 1))

__device__ __forceinline__ unsigned long long fma_f32x2(
    unsigned long long a, unsigned long long bb, unsigned long long c) {
    unsigned long long d;
    asm("fma.rn.f32x2 %0, %1, %2, %3;" : "=l"(d) : "l"(a), "l"(bb), "l"(c));
    return d;
}

// Exact two-stage value for edge outputs (head j<50 where u-padding matters,
// tail j>=n_out where appended zeros matter).
__device__ float edge_value(const float* __restrict__ x,
                            const float* __restrict__ h,
                            const float* __restrict__ b,
                            long long j, int n_in, long long n_out) {
    float acc = 0.0f;
    for (int s = 0; s < 51; s++) {
        long long k = j - s;
        if (k < 0 || k >= n_out) continue;
        long long mlo = (2 * k - 30 + 2) / 3;
        if (mlo < 0) mlo = 0;
        long long mhi = (2 * k + 32) / 3;
        if (mhi > (long long)n_in - 1) mhi = (long long)n_in - 1;
        float u = 0.0f;
        for (long long m = mlo; m <= mhi; m++) {
            long long hi = 2 * k + 32 - 3 * m;
            if (hi >= 0 && hi < 63) u = fmaf(x[m], h[hi], u);
        }
        acc = fmaf(b[s], u, acc);
    }
    return acc;
}

// Fused single kernel.
// out[j] = sum_m x[m]*C[2j+32-3m], C[r] = sum_s b[s]*h[r-2s] (r in [0,163)).
// j = jbase + g + 3*(8*l + d), G0 = 2*jbase/3 - 46 (even).
// With i = m - G0 = 16l + 2d + v:  out = sum_v xs_log[16l + 2d + v] * D_g[v],
// D_g[v] = C[2g + 170 - 3v]  (zero when index outside [0,162]), v in [0,60).
__global__ void __launch_bounds__(BLOCK_T, 3) fused_kernel(
    const float* __restrict__ x, const float* __restrict__ h,
    const float* __restrict__ b, float* __restrict__ out,
    int n_in, int n_out, int out_total)
{
    __shared__ float sbuf[SBUF_SZ];   // xs (phase 1) then os (phase 2)
    __shared__ unsigned long long cs[3][NSTEP];

    float* xs = sbuf;
    float* os = sbuf;

    int tid = threadIdx.x;
    int bx = blockIdx.x;
    int jbase = bx * OUT_PER_BLOCK;
    int G0 = (jbase / 3) * 2 - 46;   // even; global x index of logical xs[0]

    bool interior = (bx != 0) && (bx != (int)gridDim.x - 1);

    // --- tile fill issued FIRST (cp.async for interior blocks) so the
    //     coefficient FMA chain below overlaps the DRAM latency ---
    if (interior) {
        const float2* xsrc = (const float2*)(x + G0);
        #pragma unroll
        for (int q2 = tid; q2 < TILE_X / 2; q2 += BLOCK_T) {
            unsigned dst = (unsigned)__cvta_generic_to_shared(&xs[XP(2 * q2)]);
            asm volatile("cp.async.ca.shared.global [%0], [%1], 8;\n"
                         :: "r"(dst), "l"(xsrc + q2));
        }
        asm volatile("cp.async.commit_group;\n" ::: "memory");
    }

    // --- coefficient pairs, computed directly from h,b ---
    if (tid < 3 * NSTEP) {
        int g = tid / NSTEP, t = tid % NSTEP;
        float hv[2];
        #pragma unroll
        for (int qq = 0; qq < 2; qq++) {
            int v = 2 * t + qq;
            int idx = 2 * g + 170 - 3 * v;   // C index; self-guards range
            float val = 0.0f;
            if (idx >= 0 && idx <= 162) {
                #pragma unroll
                for (int s = 0; s < 51; s++) {
                    int hh = idx - 2 * s;
                    if (hh >= 0 && hh < 63) val = fmaf(__ldg(&b[s]), __ldg(&h[hh]), val);
                }
            }
            hv[qq] = val;
        }
        cs[g][t] =
            (unsigned long long)__float_as_uint(hv[0]) |
            ((unsigned long long)__float_as_uint(hv[1]) << 32);
    }

    if (interior) {
        asm volatile("cp.async.wait_group 0;\n" ::: "memory");
    } else {
        // guarded fill for first/last block
        #pragma unroll
        for (int q2 = tid; q2 < TILE_X / 2; q2 += BLOCK_T) {
            int i0 = G0 + 2 * q2;
            float2 v;
            v.x = (i0 >= 0 && i0 < n_in) ? x[i0] : 0.0f;
            v.y = (i0 + 1 >= 0 && i0 + 1 < n_in) ? x[i0 + 1] : 0.0f;
            *(float2*)&xs[XP(2 * q2)] = v;
        }
    }
    __syncthreads();

    // --- main packed FIR loop ---
    int g = tid >> 7;
    int l = tid & 127;
    const float* xb = xs + 18 * l;   // phys base of this thread's window

    // Circular packed window: slot k holds pair k (mod 8): {xs_log[16l+2k], +1}
    unsigned long long w2[8];
    #pragma unroll
    for (int k = 0; k < 8; k++)
        w2[k] = *(const unsigned long long*)&xb[XPOFF(2 * k)];

    unsigned long long acc2[R_OUT];
    #pragma unroll
    for (int d = 0; d < R_OUT; d++) acc2[d] = 0ull;

    const unsigned long long* cp = cs[g];

    #pragma unroll
    for (int t = 0; t < NSTEP; t++) {
        unsigned long long c = cp[t];
        #pragma unroll
        for (int d = 0; d < R_OUT; d++)
            acc2[d] = fma_f32x2(w2[(t + d) & 7], c, acc2[d]);
        if (t < NSTEP - 1)
            w2[t & 7] = *(const unsigned long long*)&xb[XPOFF(2 * (t + 8))];
    }

    __syncthreads();  // all xs reads done; sbuf becomes os

    // --- stage outputs: logical o = g + 24*l + 3*d, phys = o + o/24 = 25*l + g + 3*d ---
    #pragma unroll
    for (int d = 0; d < R_OUT; d++) {
        float lo = __uint_as_float((unsigned)(acc2[d] & 0xffffffffull));
        float hi = __uint_as_float((unsigned)(acc2[d] >> 32));
        os[25 * l + g + 3 * d] = lo + hi;
    }
    __syncthreads();

    // --- coalesced vectorized writeback ---
    if (jbase >= 50 && jbase + OUT_PER_BLOCK <= n_out) {
        #pragma unroll
        for (int it = 0; it < OUT_PER_BLOCK / (4 * BLOCK_T); it++) {
            int q4 = 4 * (tid + it * BLOCK_T);
            float4 v;
            v.x = os[q4 + q4 / 24];
            v.y = os[(q4 + 1) + (q4 + 1) / 24];
            v.z = os[(q4 + 2) + (q4 + 2) / 24];
            v.w = os[(q4 + 3) + (q4 + 3) / 24];
            *(float4*)&out[jbase + q4] = v;
        }
    } else {
        #pragma unroll
        for (int q = tid; q < OUT_PER_BLOCK; q += BLOCK_T) {
            int j = jbase + q;
            // j >= 50 (head handled exactly below) and j < n_out
            if ((unsigned)(j - 50) < (unsigned)(n_out - 50)) out[j] = os[q + q / 24];
        }
    }

    // --- block 0: exact edge outputs (head + tail) ---
    if (bx == 0) {
        int n_tail = out_total - n_out;
        if (tid < 50 + n_tail) {
            long long j = (tid < 50) ? (long long)tid
                                     : (long long)n_out + (tid - 50);
            out[j] = edge_value(x, h, b, j, n_in, (long long)n_out);
        }
    }
}

extern "C" void kernel_launch(void* const* d_in, const int* in_sizes, int n_in_arrs,
                              void* d_out, int out_size) {
    const float* x = (const float*)d_in[0];
    const float* h = (const float*)d_in[1];
    const float* b = (const float*)d_in[2];
    float* out = (float*)d_out;

    int n_in = in_sizes[0];  // 8 * 1048576 = 8388608
    long long n3 = (long long)n_in * 3;
    long long n_out = n3 / 2 + ((n3 % 2) ? 1 : 0);  // 12582912
    int out_total = out_size;                        // 12583008

    int grid = (int)((n_out + OUT_PER_BLOCK - 1) / OUT_PER_BLOCK);  // 4096
    fused_kernel<<<grid, BLOCK_T>>>(x, h, b, out, n_in, (int)n_out, out_total);
}

// round 12
// speedup vs baseline: 1.1023x; 1.1023x over previous
#include <cuda_runtime.h>

// Problem constants (UP=3, DOWN=2, Lh=63, Lb=51)
#define R_OUT 16                   // same-phase outputs per thread
#define BLOCK_T 384                // 3 phase groups x 128 threads
#define OUT_PER_BLOCK 6144         // 3 * 128 * R_OUT
#define TILE_X 4160                // logical floats per block (need 4154)
#define XS_PHYS 4420               // >= XP(TILE_X-1)+1
#define OS_PHYS 6272               // 6144 + 6144/48
#define SBUF_SZ 6272               // union: max(XS_PHYS, OS_PHYS)
#define NSTEP 30                   // packed coefficient steps per phase

// xs swizzle: pad TWO floats per 32 -> lane logical stride 32 becomes phys
// stride 34 (2 mod 32 banks -> LDS.64 conflict-free), 8B alignment preserved.
// With window base 32*l (multiple of 32), XP(32l + c) = 34l + XPOFF(c):
#define XP(i)    ((i) + (((i) >> 5) << 1))
#define XPOFF(c) ((c) + (((c) >> 5) << 1))   // valid when base is a multiple of 32

__device__ __forceinline__ unsigned long long fma_f32x2(
    unsigned long long a, unsigned long long bb, unsigned long long c) {
    unsigned long long d;
    asm("fma.rn.f32x2 %0, %1, %2, %3;" : "=l"(d) : "l"(a), "l"(bb), "l"(c));
    return d;
}

// Exact two-stage value for edge outputs (head j<50 where u-padding matters,
// tail j>=n_out where appended zeros matter).
__device__ float edge_value(const float* __restrict__ x,
                            const float* __restrict__ h,
                            const float* __restrict__ b,
                            long long j, int n_in, long long n_out) {
    float acc = 0.0f;
    for (int s = 0; s < 51; s++) {
        long long k = j - s;
        if (k < 0 || k >= n_out) continue;
        long long mlo = (2 * k - 30 + 2) / 3;
        if (mlo < 0) mlo = 0;
        long long mhi = (2 * k + 32) / 3;
        if (mhi > (long long)n_in - 1) mhi = (long long)n_in - 1;
        float u = 0.0f;
        for (long long m = mlo; m <= mhi; m++) {
            long long hi = 2 * k + 32 - 3 * m;
            if (hi >= 0 && hi < 63) u = fmaf(x[m], h[hi], u);
        }
        acc = fmaf(b[s], u, acc);
    }
    return acc;
}

// Fused single kernel.
// out[j] = sum_m x[m]*C[2j+32-3m], C[r] = sum_s b[s]*h[r-2s] (r in [0,163)).
// j = jbase + g + 3*(16*l + d). With Mb = 2*jbase/3 and G0 = Mb - 46 (even),
// out = sum_v xs_log[32l + 2d + v] * D_g[v], where
// D_g[v] = C[(2-g) + 3*(54 - (v - g - 2))] (zero out of range), v in [0,60).
__global__ void __launch_bounds__(BLOCK_T, 2) fused_kernel(
    const float* __restrict__ x, const float* __restrict__ h,
    const float* __restrict__ b, float* __restrict__ out,
    int n_in, int n_out, int out_total)
{
    __shared__ float sbuf[SBUF_SZ];   // xs (phase 1) then os (phase 2)
    __shared__ unsigned long long cs[3][NSTEP];

    float* xs = sbuf;
    float* os = sbuf;

    int tid = threadIdx.x;
    int bx = blockIdx.x;
    int jbase = bx * OUT_PER_BLOCK;
    int G0 = (jbase / 3) * 2 - 46;   // even; global x index of logical xs[0]

    bool interior = (bx != 0) && (bx != (int)gridDim.x - 1);

    // --- tile fill issued FIRST (cp.async, interior blocks) so the
    //     coefficient FMA chain below hides the DRAM latency ---
    if (interior) {
        const float2* xsrc = (const float2*)(x + G0);
        #pragma unroll
        for (int q2 = tid; q2 < TILE_X / 2; q2 += BLOCK_T) {
            unsigned dst = (unsigned)__cvta_generic_to_shared(&xs[XP(2 * q2)]);
            asm volatile("cp.async.ca.shared.global [%0], [%1], 8;\n"
                         :: "r"(dst), "l"(xsrc + q2));
        }
        asm volatile("cp.async.commit_group;\n" ::: "memory");
    }

    // --- coefficient pairs, computed directly from h,b ---
    if (tid < 3 * NSTEP) {
        int g = tid / NSTEP, t = tid % NSTEP;
        float hv[2];
        #pragma unroll
        for (int qq = 0; qq < 2; qq++) {
            int v = 2 * t + qq;
            int u = v - (g + 2);
            float val = 0.0f;
            if (u >= 0 && u < 55) {
                int idx = (2 - g) + 3 * (54 - u);   // C index
                if (idx >= 0 && idx <= 162) {
                    #pragma unroll
                    for (int s = 0; s < 51; s++) {
                        int hh = idx - 2 * s;
                        if (hh >= 0 && hh < 63) val = fmaf(__ldg(&b[s]), __ldg(&h[hh]), val);
                    }
                }
            }
            hv[qq] = val;
        }
        cs[g][t] =
            (unsigned long long)__float_as_uint(hv[0]) |
            ((unsigned long long)__float_as_uint(hv[1]) << 32);
    }

    if (interior) {
        asm volatile("cp.async.wait_group 0;\n" ::: "memory");
    } else {
        // guarded fill for first/last block
        #pragma unroll
        for (int q2 = tid; q2 < TILE_X / 2; q2 += BLOCK_T) {
            int i0 = G0 + 2 * q2;
            float2 v;
            v.x = (i0 >= 0 && i0 < n_in) ? x[i0] : 0.0f;
            v.y = (i0 + 1 >= 0 && i0 + 1 < n_in) ? x[i0 + 1] : 0.0f;
            *(float2*)&xs[XP(2 * q2)] = v;
        }
    }
    __syncthreads();

    // --- main packed FIR loop ---
    int g = tid >> 7;
    int l = tid & 127;
    const float* xb = xs + 34 * l;   // phys base of this thread's window

    // Circular packed window: slot k holds pair k (mod 16): {xs_log[32l+2k], +1}
    unsigned long long w2[16];
    #pragma unroll
    for (int k = 0; k < 16; k++)
        w2[k] = *(const unsigned long long*)&xb[XPOFF(2 * k)];

    unsigned long long acc2[R_OUT];
    #pragma unroll
    for (int d = 0; d < R_OUT; d++) acc2[d] = 0ull;

    const unsigned long long* cp = cs[g];

    // Coefficient prefetch only (safe: cs is read-only here). The window
    // refill stays AFTER the FMA burst: slot (t & 15) is consumed by the
    // d=0 FMA of step t, so it must not be overwritten before the burst.
    unsigned long long c_cur = cp[0];
    #pragma unroll
    for (int t = 0; t < NSTEP; t++) {
        unsigned long long c_nxt = (t < NSTEP - 1) ? cp[t + 1] : 0ull;
        #pragma unroll
        for (int d = 0; d < R_OUT; d++)
            acc2[d] = fma_f32x2(w2[(t + d) & 15], c_cur, acc2[d]);
        if (t < NSTEP - 1)
            w2[t & 15] = *(const unsigned long long*)&xb[XPOFF(2 * (t + 16))];
        c_cur = c_nxt;
    }

    __syncthreads();  // all xs reads done; sbuf becomes os

    // --- stage outputs: logical o = g + 48*l + 3*d, phys = 49*l + g + 3*d ---
    #pragma unroll
    for (int d = 0; d < R_OUT; d++) {
        float lo = __uint_as_float((unsigned)(acc2[d] & 0xffffffffull));
        float hi = __uint_as_float((unsigned)(acc2[d] >> 32));
        os[49 * l + g + 3 * d] = lo + hi;
    }
    __syncthreads();

    // --- coalesced vectorized writeback ---
    if (jbase >= 50 && jbase + OUT_PER_BLOCK <= n_out) {
        #pragma unroll
        for (int it = 0; it < OUT_PER_BLOCK / (4 * BLOCK_T); it++) {
            int q4 = 4 * (tid + it * BLOCK_T);
            float4 v;
            v.x = os[q4 + q4 / 48];
            v.y = os[(q4 + 1) + (q4 + 1) / 48];
            v.z = os[(q4 + 2) + (q4 + 2) / 48];
            v.w = os[(q4 + 3) + (q4 + 3) / 48];
            *(float4*)&out[jbase + q4] = v;
        }
    } else {
        #pragma unroll
        for (int q = tid; q < OUT_PER_BLOCK; q += BLOCK_T) {
            int j = jbase + q;
            // j >= 50 (head handled exactly below) and j < n_out
            if ((unsigned)(j - 50) < (unsigned)(n_out - 50)) out[j] = os[q + q / 48];
        }
    }

    // --- block 0: exact edge outputs (head + tail) ---
    if (bx == 0) {
        int n_tail = out_total - n_out;
        if (tid < 50 + n_tail) {
            long long j = (tid < 50) ? (long long)tid
                                     : (long long)n_out + (tid - 50);
            out[j] = edge_value(x, h, b, j, n_in, (long long)n_out);
        }
    }
}

extern "C" void kernel_launch(void* const* d_in, const int* in_sizes, int n_in_arrs,
                              void* d_out, int out_size) {
    const float* x = (const float*)d_in[0];
    const float* h = (const float*)d_in[1];
    const float* b = (const float*)d_in[2];
    float* out = (float*)d_out;

    int n_in = in_sizes[0];  // 8 * 1048576 = 8388608
    long long n3 = (long long)n_in * 3;
    long long n_out = n3 / 2 + ((n3 % 2) ? 1 : 0);  // 12582912
    int out_total = out_size;                        // 12583008

    int grid = (int)((n_out + OUT_PER_BLOCK - 1) / OUT_PER_BLOCK);  // 2048
    fused_kernel<<<grid, BLOCK_T>>>(x, h, b, out, n_in, (int)n_out, out_total);
}

// round 13
// speedup vs baseline: 1.1870x; 1.0768x over previous
#include <cuda_runtime.h>

// Problem constants (UP=3, DOWN=2, Lh=63, Lb=51)
#define R_OUT 16                   // same-phase outputs per thread
#define BLOCK_T 384                // 3 phase groups x 128 threads
#define OUT_PER_BLOCK 6144         // 3 * 128 * R_OUT
#define TILE_X 4160                // logical floats per block (need 4154)
#define XS_PHYS 4420               // >= XP(TILE_X-1)+1
#define OS_GRP 1568                // per lane-group staging slice (1536 + pad)
#define NSTEP 29                   // packed coefficient steps (v in [2,60))

// xs swizzle: pad TWO floats per 32 -> lane logical stride 32 becomes phys
// stride 34 (2 mod 32 banks -> LDS.64 conflict-free), 8B alignment preserved.
// With window base 32*l, XP(32l + e) = 34l + XPOFF(e) for any e >= 0:
#define XP(i)    ((i) + (((i) >> 5) << 1))
#define XPOFF(e) ((e) + (((e) >> 5) << 1))

__device__ __forceinline__ unsigned long long fma_f32x2(
    unsigned long long a, unsigned long long bb, unsigned long long c) {
    unsigned long long d;
    asm("fma.rn.f32x2 %0, %1, %2, %3;" : "=l"(d) : "l"(a), "l"(bb), "l"(c));
    return d;
}

// Exact two-stage value for edge outputs (head j<50 where u-padding matters,
// tail j>=n_out where appended zeros matter).
__device__ float edge_value(const float* __restrict__ x,
                            const float* __restrict__ h,
                            const float* __restrict__ b,
                            long long j, int n_in, long long n_out) {
    float acc = 0.0f;
    for (int s = 0; s < 51; s++) {
        long long k = j - s;
        if (k < 0 || k >= n_out) continue;
        long long mlo = (2 * k - 30 + 2) / 3;
        if (mlo < 0) mlo = 0;
        long long mhi = (2 * k + 32) / 3;
        if (mhi > (long long)n_in - 1) mhi = (long long)n_in - 1;
        float u = 0.0f;
        for (long long m = mlo; m <= mhi; m++) {
            long long hi = 2 * k + 32 - 3 * m;
            if (hi >= 0 && hi < 63) u = fmaf(x[m], h[hi], u);
        }
        acc = fmaf(b[s], u, acc);
    }
    return acc;
}

// Fused single kernel.
// out[j] = sum_m x[m]*C[2j+32-3m], C[r] = sum_s b[s]*h[r-2s] (r in [0,163)).
// j = jbase + g + 3*(16*l + d), G0 = 2*jbase/3 - 46 (even).
// With i = m - G0 = 32l + 2d + v:  out = sum_v xs_log[32l+2d+v] * D_g[v],
// D_g[v] = C[2g + 170 - 3v] (zero outside [0,162]); nonzero v in [3,59)
// for all g, so v in [2,60) with 29 packed steps suffices.
__global__ void __launch_bounds__(BLOCK_T, 2) fused_kernel(
    const float* __restrict__ x, const float* __restrict__ h,
    const float* __restrict__ b, float* __restrict__ out,
    int n_in, int n_out, int out_total)
{
    __shared__ float xs[XS_PHYS];
    __shared__ float os[4 * OS_GRP];          // per-lane-group staging slices
    __shared__ unsigned long long cs[3][NSTEP];

    int tid = threadIdx.x;
    int bx = blockIdx.x;
    int jbase = bx * OUT_PER_BLOCK;
    int G0 = (jbase / 3) * 2 - 46;   // even; global x index of logical xs[0]

    bool interior = (bx != 0) && (bx != (int)gridDim.x - 1);

    // --- tile fill issued FIRST (cp.async, interior blocks) so the
    //     coefficient FMA chain below hides the DRAM latency ---
    if (interior) {
        const float2* xsrc = (const float2*)(x + G0);
        #pragma unroll
        for (int q2 = tid; q2 < TILE_X / 2; q2 += BLOCK_T) {
            unsigned dst = (unsigned)__cvta_generic_to_shared(&xs[XP(2 * q2)]);
            asm volatile("cp.async.ca.shared.global [%0], [%1], 8;\n"
                         :: "r"(dst), "l"(xsrc + q2));
        }
        asm volatile("cp.async.commit_group;\n" ::: "memory");
    }

    // --- coefficient pairs, computed directly from h,b ---
    // cs[g][t] = (D_g[2+2t], D_g[3+2t]) = (C[2g+164-6t], C[2g+161-6t])
    if (tid < 3 * NSTEP) {
        int g = tid / NSTEP, t = tid % NSTEP;
        float hv[2];
        #pragma unroll
        for (int qq = 0; qq < 2; qq++) {
            int idx = 2 * g + 164 - 6 * t - 3 * qq;   // C index
            float val = 0.0f;
            if (idx >= 0 && idx <= 162) {
                #pragma unroll
                for (int s = 0; s < 51; s++) {
                    int hh = idx - 2 * s;
                    if (hh >= 0 && hh < 63) val = fmaf(__ldg(&b[s]), __ldg(&h[hh]), val);
                }
            }
            hv[qq] = val;
        }
        cs[g][t] =
            (unsigned long long)__float_as_uint(hv[0]) |
            ((unsigned long long)__float_as_uint(hv[1]) << 32);
    }

    if (interior) {
        asm volatile("cp.async.wait_group 0;\n" ::: "memory");
    } else {
        // guarded fill for first/last block
        #pragma unroll
        for (int q2 = tid; q2 < TILE_X / 2; q2 += BLOCK_T) {
            int i0 = G0 + 2 * q2;
            float2 v;
            v.x = (i0 >= 0 && i0 < n_in) ? x[i0] : 0.0f;
            v.y = (i0 + 1 >= 0 && i0 + 1 < n_in) ? x[i0 + 1] : 0.0f;
            *(float2*)&xs[XP(2 * q2)] = v;
        }
    }
    __syncthreads();   // xs + cs ready (the ONLY block-wide barrier)

    // --- main packed FIR loop ---
    int g = tid >> 7;
    int l = tid & 127;
    const float* xb = xs + 34 * l;   // phys base of this thread's window

    // Circular packed window: slot k holds pair at v-offset 2+2k:
    // {xs_log[32l+2+2k], xs_log[32l+3+2k]}
    unsigned long long w2[16];
    #pragma unroll
    for (int k = 0; k < 16; k++)
        w2[k] = *(const unsigned long long*)&xb[XPOFF(2 + 2 * k)];

    unsigned long long acc2[R_OUT];
    #pragma unroll
    for (int d = 0; d < R_OUT; d++) acc2[d] = 0ull;

    const unsigned long long* cp = cs[g];

    unsigned long long c_cur = cp[0];
    #pragma unroll
    for (int t = 0; t < NSTEP; t++) {
        unsigned long long c_nxt = (t < NSTEP - 1) ? cp[t + 1] : 0ull;
        #pragma unroll
        for (int d = 0; d < R_OUT; d++)
            acc2[d] = fma_f32x2(w2[(t + d) & 15], c_cur, acc2[d]);
        if (t < NSTEP - 1)
            w2[t & 15] = *(const unsigned long long*)&xb[XPOFF(2 + 2 * (t + 16))];
        c_cur = c_nxt;
    }

    // --- group-local staging (no block-wide barrier) ---
    // lane-group w = l>>5 covers contiguous outputs [jbase+1536w, +1536):
    // group-local logical oo = g + 3*(16*ll + d), ll = l&31, phys stride 49.
    int w = l >> 5;
    int ll = l & 31;
    float* og = os + OS_GRP * w;
    #pragma unroll
    for (int d = 0; d < R_OUT; d++) {
        float lo = __uint_as_float((unsigned)(acc2[d] & 0xffffffffull));
        float hi = __uint_as_float((unsigned)(acc2[d] >> 32));
        og[49 * ll + g + 3 * d] = lo + hi;
    }
    // 3-warp rendezvous: warps {w, w+4, w+8} (96 threads), barrier id w+1
    asm volatile("bar.sync %0, 96;" :: "r"(w + 1) : "memory");

    // --- group-local coalesced writeback ---
    int jgrp = jbase + 1536 * w;
    int tt = (g << 5) + ll;            // group-internal thread index [0,96)
    if (jgrp >= 50 && jgrp + 1536 <= n_out) {
        #pragma unroll
        for (int it = 0; it < 4; it++) {
            int q4 = 4 * tt + 384 * it;
            int ph = q4 + q4 / 48;
            float4 v;
            v.x = og[ph];
            v.y = og[ph + 1];
            v.z = og[ph + 2];
            v.w = og[ph + 3];
            *(float4*)&out[jgrp + q4] = v;
        }
    } else {
        #pragma unroll
        for (int q = tt; q < 1536; q += 96) {
            int j = jgrp + q;
            // j >= 50 (head handled exactly below) and j < n_out
            if ((unsigned)(j - 50) < (unsigned)(n_out - 50)) out[j] = og[q + q / 48];
        }
    }

    // --- block 0: exact edge outputs (head + tail) ---
    if (bx == 0) {
        int n_tail = out_total - n_out;
        if (tid < 50 + n_tail) {
            long long j = (tid < 50) ? (long long)tid
                                     : (long long)n_out + (tid - 50);
            out[j] = edge_value(x, h, b, j, n_in, (long long)n_out);
        }
    }
}

extern "C" void kernel_launch(void* const* d_in, const int* in_sizes, int n_in_arrs,
                              void* d_out, int out_size) {
    const float* x = (const float*)d_in[0];
    const float* h = (const float*)d_in[1];
    const float* b = (const float*)d_in[2];
    float* out = (float*)d_out;

    int n_in = in_sizes[0];  // 8 * 1048576 = 8388608
    long long n3 = (long long)n_in * 3;
    long long n_out = n3 / 2 + ((n3 % 2) ? 1 : 0);  // 12582912
    int out_total = out_size;                        // 12583008

    int grid = (int)((n_out + OUT_PER_BLOCK - 1) / OUT_PER_BLOCK);  // 2048
    fused_kernel<<<grid, BLOCK_T>>>(x, h, b, out, n_in, (int)n_out, out_total);
}